// round 1
// baseline (speedup 1.0000x reference)
#include <cuda_runtime.h>
#include <math.h>

#define NN 100000
#define EE 1600000
#define HH 128
#define CC 64
#define SCAN_BLOCKS 98   // ceil(100000/1024)

// ---------------- scratch (device globals; no allocation allowed) ----------------
__device__ float g_mean[(size_t)NN * HH];   // aggregated mean features / reused as final h
__device__ float g_pre [(size_t)NN * HH];   // conv output (pre-BN, L2-normalized)
__device__ float g_h1  [(size_t)NN * HH];   // layer-1 activation (residual)
__device__ int   g_es[EE];
__device__ int   g_ed[EE];
__device__ int   g_csr[EE];
__device__ int   g_deg[NN];
__device__ int   g_rs[NN];
__device__ int   g_cur[NN];
__device__ int   g_bsum[SCAN_BLOCKS];
__device__ int   g_boff[SCAN_BLOCKS];
__device__ int   g_is64;
__device__ float g_colsum[HH];
__device__ float g_colsq[HH];
__device__ float g_scale[HH];
__device__ float g_shift[HH];

// ---------------- edge preprocessing ----------------
__global__ void detect_k(const int* __restrict__ ei) {
    // int64 indices < 2^31 have zero high words at odd int32 positions.
    int ored = ei[1] | ei[3] | ei[5] | ei[7] | ei[9] | ei[11] | ei[13] | ei[15];
    g_is64 = (ored == 0) ? 1 : 0;
}

__global__ void zero_deg_k() {
    int i = blockIdx.x * blockDim.x + threadIdx.x;
    if (i < NN) g_deg[i] = 0;
}

__global__ void edge_conv_k(const int* __restrict__ ei) {
    int e = blockIdx.x * blockDim.x + threadIdx.x;
    if (e >= EE) return;
    int s, d;
    if (g_is64) {
        s = ei[2 * e];
        d = ei[2 * (EE + e)];
    } else {
        s = ei[e];
        d = ei[EE + e];
    }
    g_es[e] = s;
    g_ed[e] = d;
    atomicAdd(&g_deg[d], 1);
}

__global__ void scan1_k() {
    __shared__ int sh[1024];
    int tid = threadIdx.x;
    int i = blockIdx.x * 1024 + tid;
    int v = (i < NN) ? g_deg[i] : 0;
    sh[tid] = v;
    __syncthreads();
    for (int off = 1; off < 1024; off <<= 1) {
        int t = (tid >= off) ? sh[tid - off] : 0;
        __syncthreads();
        sh[tid] += t;
        __syncthreads();
    }
    if (i < NN) g_rs[i] = sh[tid] - v;   // exclusive
    if (tid == 1023) g_bsum[blockIdx.x] = sh[1023];
}

__global__ void scan2_k() {
    int run = 0;
    for (int b = 0; b < SCAN_BLOCKS; b++) { g_boff[b] = run; run += g_bsum[b]; }
}

__global__ void scan3_k() {
    int i = blockIdx.x * 1024 + threadIdx.x;
    if (i < NN) {
        int v = g_rs[i] + g_boff[blockIdx.x];
        g_rs[i] = v;
        g_cur[i] = v;
    }
}

__global__ void csr_fill_k() {
    int e = blockIdx.x * blockDim.x + threadIdx.x;
    if (e >= EE) return;
    int p = atomicAdd(&g_cur[g_ed[e]], 1);
    g_csr[p] = g_es[e];
}

// ---------------- mean aggregation (warp per node) ----------------
__global__ void aggregate_k(const float* __restrict__ X, float* __restrict__ Out) {
    int warp = (blockIdx.x * blockDim.x + threadIdx.x) >> 5;
    int lane = threadIdx.x & 31;
    if (warp >= NN) return;
    int rs = g_rs[warp];
    int d  = g_deg[warp];
    const float4* X4 = (const float4*)X;
    float4 acc = make_float4(0.f, 0.f, 0.f, 0.f);
    for (int j0 = 0; j0 < d; j0 += 32) {
        int idx = 0;
        if (j0 + lane < d) idx = g_csr[rs + j0 + lane];
        int cnt = min(32, d - j0);
        for (int t = 0; t < cnt; t++) {
            int s = __shfl_sync(0xffffffffu, idx, t);
            float4 v = X4[(size_t)s * 32 + lane];
            acc.x += v.x; acc.y += v.y; acc.z += v.z; acc.w += v.w;
        }
    }
    float inv = 1.0f / fmaxf((float)d, 1.0f);
    float4 o = make_float4(acc.x * inv, acc.y * inv, acc.z * inv, acc.w * inv);
    *(float4*)(Out + (size_t)warp * 128 + lane * 4) = o;
}

// ---------------- fused SAGE GEMM: C = Xm@Wl^T + Xr@Wr^T + b, row-L2-normalized ----------------
__global__ __launch_bounds__(256, 2) void sage_gemm_norm(
    const float* __restrict__ Xm, const float* __restrict__ Xr,
    const float* __restrict__ Wl, const float* __restrict__ Wr,
    const float* __restrict__ bias, float* __restrict__ Out)
{
    __shared__ float sAm[8][132];
    __shared__ float sAx[8][132];
    __shared__ float sBl[8][132];
    __shared__ float sBr[8][132];
    __shared__ float rowsq[128];

    const int tid = threadIdx.x;
    const int tx = tid & 15;      // col group (cols tx*8 .. +7)
    const int ty = tid >> 4;      // row group (rows ty*8 .. +7)
    const int row0 = blockIdx.x * 128;
    const int lm = tid >> 1;            // 0..127 : tile row (A) / W row (B)
    const int lk = (tid & 1) * 4;       // k-quad

    float c[8][8];
#pragma unroll
    for (int i = 0; i < 8; i++)
#pragma unroll
        for (int j = 0; j < 8; j++) c[i][j] = 0.f;

    for (int k0 = 0; k0 < 128; k0 += 8) {
        int grow = row0 + lm;
        float4 am4 = make_float4(0.f,0.f,0.f,0.f), ax4 = am4;
        if (grow < NN) {
            am4 = *(const float4*)(Xm + (size_t)grow * 128 + k0 + lk);
            ax4 = *(const float4*)(Xr + (size_t)grow * 128 + k0 + lk);
        }
        float4 bl4 = *(const float4*)(Wl + lm * 128 + k0 + lk);
        float4 br4 = *(const float4*)(Wr + lm * 128 + k0 + lk);
        __syncthreads();
        sAm[lk+0][lm] = am4.x; sAm[lk+1][lm] = am4.y; sAm[lk+2][lm] = am4.z; sAm[lk+3][lm] = am4.w;
        sAx[lk+0][lm] = ax4.x; sAx[lk+1][lm] = ax4.y; sAx[lk+2][lm] = ax4.z; sAx[lk+3][lm] = ax4.w;
        sBl[lk+0][lm] = bl4.x; sBl[lk+1][lm] = bl4.y; sBl[lk+2][lm] = bl4.z; sBl[lk+3][lm] = bl4.w;
        sBr[lk+0][lm] = br4.x; sBr[lk+1][lm] = br4.y; sBr[lk+2][lm] = br4.z; sBr[lk+3][lm] = br4.w;
        __syncthreads();
#pragma unroll
        for (int k = 0; k < 8; k++) {
            float am[8], ax[8], bl[8], br[8];
            *(float4*)&am[0] = *(const float4*)&sAm[k][ty * 8];
            *(float4*)&am[4] = *(const float4*)&sAm[k][ty * 8 + 4];
            *(float4*)&ax[0] = *(const float4*)&sAx[k][ty * 8];
            *(float4*)&ax[4] = *(const float4*)&sAx[k][ty * 8 + 4];
            *(float4*)&bl[0] = *(const float4*)&sBl[k][tx * 8];
            *(float4*)&bl[4] = *(const float4*)&sBl[k][tx * 8 + 4];
            *(float4*)&br[0] = *(const float4*)&sBr[k][tx * 8];
            *(float4*)&br[4] = *(const float4*)&sBr[k][tx * 8 + 4];
#pragma unroll
            for (int i = 0; i < 8; i++)
#pragma unroll
                for (int j = 0; j < 8; j++) {
                    c[i][j] = fmaf(am[i], bl[j], c[i][j]);
                    c[i][j] = fmaf(ax[i], br[j], c[i][j]);
                }
        }
    }
    __syncthreads();
    if (tid < 128) rowsq[tid] = 0.f;
    float breg[8];
#pragma unroll
    for (int j = 0; j < 8; j++) breg[j] = bias[tx * 8 + j];
    __syncthreads();
#pragma unroll
    for (int i = 0; i < 8; i++) {
        float p = 0.f;
#pragma unroll
        for (int j = 0; j < 8; j++) {
            float y = c[i][j] + breg[j];
            c[i][j] = y;
            p = fmaf(y, y, p);
        }
        atomicAdd(&rowsq[ty * 8 + i], p);
    }
    __syncthreads();
#pragma unroll
    for (int i = 0; i < 8; i++) {
        int grow = row0 + ty * 8 + i;
        if (grow >= NN) continue;
        float inv = 1.0f / fmaxf(sqrtf(rowsq[ty * 8 + i]), 1e-12f);
        float4 o0 = make_float4(c[i][0]*inv, c[i][1]*inv, c[i][2]*inv, c[i][3]*inv);
        float4 o1 = make_float4(c[i][4]*inv, c[i][5]*inv, c[i][6]*inv, c[i][7]*inv);
        *(float4*)(Out + (size_t)grow * 128 + tx * 8)     = o0;
        *(float4*)(Out + (size_t)grow * 128 + tx * 8 + 4) = o1;
    }
}

// ---------------- batch norm ----------------
__global__ void zero_bn_k() {
    int t = threadIdx.x;
    if (t < HH) { g_colsum[t] = 0.f; g_colsq[t] = 0.f; }
}

__global__ void bn_stats_k(const float* __restrict__ X) {
    __shared__ float ssum[256], ssq[256];
    int col  = threadIdx.x & 127;
    int half = threadIdx.x >> 7;
    float s = 0.f, q = 0.f;
    for (int row = blockIdx.x * 2 + half; row < NN; row += gridDim.x * 2) {
        float v = X[(size_t)row * 128 + col];
        s += v;
        q = fmaf(v, v, q);
    }
    ssum[threadIdx.x] = s;
    ssq[threadIdx.x]  = q;
    __syncthreads();
    if (half == 0) {
        s = ssum[col] + ssum[col + 128];
        q = ssq[col] + ssq[col + 128];
        atomicAdd(&g_colsum[col], s);
        atomicAdd(&g_colsq[col], q);
    }
}

__global__ void bn_finalize_k(const float* __restrict__ gamma, const float* __restrict__ beta) {
    int c = threadIdx.x;
    if (c >= HH) return;
    float mu  = g_colsum[c] * (1.0f / NN);
    float var = g_colsq[c] * (1.0f / NN) - mu * mu;
    float sc  = gamma[c] * rsqrtf(var + 1e-5f);
    g_scale[c] = sc;
    g_shift[c] = beta[c] - mu * sc;
}

__global__ void bn_apply_k(const float* __restrict__ pre, const float* __restrict__ res,
                           float* __restrict__ out, int has_res) {
    int idx = blockIdx.x * blockDim.x + threadIdx.x;
    if (idx >= NN * HH) return;
    int col = idx & 127;
    float v = fmaf(pre[idx], g_scale[col], g_shift[col]);
    v = fmaxf(v, 0.f);
    if (has_res) v += res[idx];
    out[idx] = v;
}

// ---------------- output GEMM: logits = X@Wout^T + b ----------------
__global__ __launch_bounds__(256) void out_gemm_k(
    const float* __restrict__ X, const float* __restrict__ W,
    const float* __restrict__ bias, float* __restrict__ Out)
{
    __shared__ float sA[8][132];
    __shared__ float sB[8][68];
    const int tid = threadIdx.x;
    const int tx = tid & 15;     // cols tx*4 .. +3
    const int ty = tid >> 4;     // rows ty*8 .. +7
    const int row0 = blockIdx.x * 128;
    float c[8][4];
#pragma unroll
    for (int i = 0; i < 8; i++)
#pragma unroll
        for (int j = 0; j < 4; j++) c[i][j] = 0.f;

    const int lm = tid >> 1;
    const int lk = (tid & 1) * 4;
    for (int k0 = 0; k0 < 128; k0 += 8) {
        int grow = row0 + lm;
        float4 a4 = make_float4(0.f,0.f,0.f,0.f);
        if (grow < NN) a4 = *(const float4*)(X + (size_t)grow * 128 + k0 + lk);
        float4 w4 = make_float4(0.f,0.f,0.f,0.f);
        if (tid < 128) w4 = *(const float4*)(W + lm * 128 + k0 + lk);
        __syncthreads();
        sA[lk+0][lm] = a4.x; sA[lk+1][lm] = a4.y; sA[lk+2][lm] = a4.z; sA[lk+3][lm] = a4.w;
        if (tid < 128) {
            sB[lk+0][lm] = w4.x; sB[lk+1][lm] = w4.y; sB[lk+2][lm] = w4.z; sB[lk+3][lm] = w4.w;
        }
        __syncthreads();
#pragma unroll
        for (int k = 0; k < 8; k++) {
            float a[8], b[4];
            *(float4*)&a[0] = *(const float4*)&sA[k][ty * 8];
            *(float4*)&a[4] = *(const float4*)&sA[k][ty * 8 + 4];
            *(float4*)&b[0] = *(const float4*)&sB[k][tx * 4];
#pragma unroll
            for (int i = 0; i < 8; i++)
#pragma unroll
                for (int j = 0; j < 4; j++)
                    c[i][j] = fmaf(a[i], b[j], c[i][j]);
        }
    }
    float breg[4];
#pragma unroll
    for (int j = 0; j < 4; j++) breg[j] = bias[tx * 4 + j];
#pragma unroll
    for (int i = 0; i < 8; i++) {
        int grow = row0 + ty * 8 + i;
        if (grow >= NN) continue;
        float4 o = make_float4(c[i][0]+breg[0], c[i][1]+breg[1], c[i][2]+breg[2], c[i][3]+breg[3]);
        *(float4*)(Out + (size_t)grow * 64 + tx * 4) = o;
    }
}

// ---------------- log_softmax (warp per row, 64 cols) ----------------
__global__ void log_softmax_k(float* __restrict__ Out) {
    int row = blockIdx.x * 8 + (threadIdx.x >> 5);
    if (row >= NN) return;
    int lane = threadIdx.x & 31;
    float* p = Out + (size_t)row * 64;
    float v0 = p[lane];
    float v1 = p[lane + 32];
    float m = fmaxf(v0, v1);
#pragma unroll
    for (int off = 16; off > 0; off >>= 1)
        m = fmaxf(m, __shfl_xor_sync(0xffffffffu, m, off));
    float s = expf(v0 - m) + expf(v1 - m);
#pragma unroll
    for (int off = 16; off > 0; off >>= 1)
        s += __shfl_xor_sync(0xffffffffu, s, off);
    float l = m + logf(s);
    p[lane]      = v0 - l;
    p[lane + 32] = v1 - l;
}

// ---------------- launch ----------------
extern "C" void kernel_launch(void* const* d_in, const int* in_sizes, int n_in,
                              void* d_out, int out_size) {
    const float* x    = (const float*)d_in[0];
    const int*   ei   = (const int*)  d_in[1];
    const float* W1l  = (const float*)d_in[2];
    const float* b1l  = (const float*)d_in[3];
    const float* W1r  = (const float*)d_in[4];
    const float* g1   = (const float*)d_in[5];
    const float* be1  = (const float*)d_in[6];
    const float* W2l  = (const float*)d_in[7];
    const float* b2l  = (const float*)d_in[8];
    const float* W2r  = (const float*)d_in[9];
    const float* g2   = (const float*)d_in[10];
    const float* be2  = (const float*)d_in[11];
    const float* Wout = (const float*)d_in[12];
    const float* bout = (const float*)d_in[13];
    float* out = (float*)d_out;

    float *p_mean, *p_pre, *p_h1;
    cudaGetSymbolAddress((void**)&p_mean, g_mean);
    cudaGetSymbolAddress((void**)&p_pre,  g_pre);
    cudaGetSymbolAddress((void**)&p_h1,   g_h1);

    const int ETHREADS = 256;
    const int EGRID = (EE + ETHREADS - 1) / ETHREADS;
    const int GEMM_GRID = (NN + 127) / 128;   // 782
    const int AGG_GRID = (NN * 32 + 255) / 256;   // 12500
    const int EW_GRID = (NN * HH) / 256;      // 50000

    // edge preprocessing (shared by both convs)
    detect_k<<<1, 1>>>(ei);
    zero_deg_k<<<(NN + 255) / 256, 256>>>();
    edge_conv_k<<<EGRID, ETHREADS>>>(ei);
    scan1_k<<<SCAN_BLOCKS, 1024>>>();
    scan2_k<<<1, 1>>>();
    scan3_k<<<SCAN_BLOCKS, 1024>>>();
    csr_fill_k<<<EGRID, ETHREADS>>>();

    // ---- conv1 ----
    aggregate_k<<<AGG_GRID, 256>>>(x, p_mean);
    sage_gemm_norm<<<GEMM_GRID, 256>>>(p_mean, x, W1l, W1r, b1l, p_pre);
    zero_bn_k<<<1, 128>>>();
    bn_stats_k<<<512, 256>>>(p_pre);
    bn_finalize_k<<<1, 128>>>(g1, be1);
    bn_apply_k<<<EW_GRID, 256>>>(p_pre, p_h1, p_h1, 0);

    // ---- conv2 (+ residual) ----
    aggregate_k<<<AGG_GRID, 256>>>(p_h1, p_mean);
    sage_gemm_norm<<<GEMM_GRID, 256>>>(p_mean, p_h1, W2l, W2r, b2l, p_pre);
    zero_bn_k<<<1, 128>>>();
    bn_stats_k<<<512, 256>>>(p_pre);
    bn_finalize_k<<<1, 128>>>(g2, be2);
    bn_apply_k<<<EW_GRID, 256>>>(p_pre, p_h1, p_mean, 1);

    // ---- output head ----
    out_gemm_k<<<GEMM_GRID, 256>>>(p_mean, Wout, bout, out);
    log_softmax_k<<<(NN + 7) / 8, 256>>>(out);
}

// round 3
// speedup vs baseline: 1.1443x; 1.1443x over previous
#include <cuda_runtime.h>
#include <cuda_bf16.h>
#include <math.h>
#include <stdint.h>

#define NN 100000
#define EE 1600000
#define HH 128
#define CC 64
#define SCAN_BLOCKS 98   // ceil(100000/1024)

// ---------------- scratch (device globals; no allocation allowed) ----------------
__device__ float g_pre [(size_t)NN * HH];   // conv output (post-norm, pre-BN)
__device__ float g_h1  [(size_t)NN * HH];   // layer-1 activation (residual)
__device__ __nv_bfloat16 g_mh[(size_t)NN * HH];  // mean hi / later hfinal hi
__device__ __nv_bfloat16 g_ml[(size_t)NN * HH];  // mean lo
__device__ __nv_bfloat16 g_xh[(size_t)NN * HH];  // Xr hi (x then h1)
__device__ __nv_bfloat16 g_xl[(size_t)NN * HH];  // Xr lo
__device__ __nv_bfloat16 g_wh[4 * HH * HH + CC * HH];
__device__ __nv_bfloat16 g_wl[4 * HH * HH + CC * HH];
__device__ int   g_es[EE];
__device__ int   g_ed[EE];
__device__ int   g_csr[EE];
__device__ int   g_deg[NN];
__device__ int   g_rs[NN];
__device__ int   g_cur[NN];
__device__ int   g_bsum[SCAN_BLOCKS];
__device__ int   g_boff[SCAN_BLOCKS];
__device__ int   g_is64;
__device__ float g_colsum[HH];
__device__ float g_colsq[HH];
__device__ float g_scale[HH];
__device__ float g_shift[HH];

// ==================== warp-MMA helpers (sm_80 PTX, runs on sm_100 base) ====================
__device__ __forceinline__ uint32_t smem_u32(const void* p) {
    uint32_t a;
    asm("{ .reg .u64 t; cvta.to.shared.u64 t, %1; cvt.u32.u64 %0, t; }" : "=r"(a) : "l"(p));
    return a;
}

#define LDSM4(r0, r1, r2, r3, a) \
    asm volatile("ldmatrix.sync.aligned.m8n8.x4.shared.b16 {%0,%1,%2,%3}, [%4];" \
                 : "=r"(r0), "=r"(r1), "=r"(r2), "=r"(r3) : "r"(a))

#define MMA16816(c, a0, a1, a2, a3, b0, b1) \
    asm volatile("mma.sync.aligned.m16n8k16.row.col.f32.bf16.bf16.f32 " \
                 "{%0,%1,%2,%3},{%4,%5,%6,%7},{%8,%9},{%0,%1,%2,%3};" \
                 : "+f"((c)[0]), "+f"((c)[1]), "+f"((c)[2]), "+f"((c)[3]) \
                 : "r"(a0), "r"(a1), "r"(a2), "r"(a3), "r"(b0), "r"(b1))

// ---------------- edge preprocessing ----------------
__global__ void detect_k(const int* __restrict__ ei) {
    int ored = ei[1] | ei[3] | ei[5] | ei[7] | ei[9] | ei[11] | ei[13] | ei[15];
    g_is64 = (ored == 0) ? 1 : 0;
}

__global__ void zero_deg_k() {
    int i = blockIdx.x * blockDim.x + threadIdx.x;
    if (i < NN) g_deg[i] = 0;
}

__global__ void edge_conv_k(const int* __restrict__ ei) {
    int e = blockIdx.x * blockDim.x + threadIdx.x;
    if (e >= EE) return;
    int s, d;
    if (g_is64) { s = ei[2 * e]; d = ei[2 * (EE + e)]; }
    else        { s = ei[e];     d = ei[EE + e]; }
    g_es[e] = s;
    g_ed[e] = d;
    atomicAdd(&g_deg[d], 1);
}

__global__ void scan1_k() {
    __shared__ int sh[1024];
    int tid = threadIdx.x;
    int i = blockIdx.x * 1024 + tid;
    int v = (i < NN) ? g_deg[i] : 0;
    sh[tid] = v;
    __syncthreads();
    for (int off = 1; off < 1024; off <<= 1) {
        int t = (tid >= off) ? sh[tid - off] : 0;
        __syncthreads();
        sh[tid] += t;
        __syncthreads();
    }
    if (i < NN) g_rs[i] = sh[tid] - v;
    if (tid == 1023) g_bsum[blockIdx.x] = sh[1023];
}

__global__ void scan2_k() {
    int run = 0;
    for (int b = 0; b < SCAN_BLOCKS; b++) { g_boff[b] = run; run += g_bsum[b]; }
}

__global__ void scan3_k() {
    int i = blockIdx.x * 1024 + threadIdx.x;
    if (i < NN) {
        int v = g_rs[i] + g_boff[blockIdx.x];
        g_rs[i] = v;
        g_cur[i] = v;
    }
}

__global__ void csr_fill_k() {
    int e = blockIdx.x * blockDim.x + threadIdx.x;
    if (e >= EE) return;
    int p = atomicAdd(&g_cur[g_ed[e]], 1);
    g_csr[p] = g_es[e];
}

// ---------------- weight / input conversion to bf16 hi+lo ----------------
__global__ void wprep_k(const float* __restrict__ W1l, const float* __restrict__ W1r,
                        const float* __restrict__ W2l, const float* __restrict__ W2r,
                        const float* __restrict__ Wout) {
    int i = blockIdx.x * blockDim.x + threadIdx.x;
    if (i >= 4 * 16384 + 8192) return;
    float v;
    if (i < 16384)      v = W1l[i];
    else if (i < 32768) v = W1r[i - 16384];
    else if (i < 49152) v = W2l[i - 32768];
    else if (i < 65536) v = W2r[i - 49152];
    else                v = Wout[i - 65536];
    __nv_bfloat16 h = __float2bfloat16(v);
    g_wh[i] = h;
    g_wl[i] = __float2bfloat16(v - __bfloat162float(h));
}

__global__ void xconv_k(const float* __restrict__ x) {
    int i = blockIdx.x * blockDim.x + threadIdx.x;
    if (i >= NN * HH) return;
    float v = x[i];
    __nv_bfloat16 h = __float2bfloat16(v);
    g_xh[i] = h;
    g_xl[i] = __float2bfloat16(v - __bfloat162float(h));
}

// ---------------- mean aggregation (warp per node) -> bf16 hi/lo ----------------
__global__ void aggregate_k(const float* __restrict__ X) {
    int warp = (blockIdx.x * blockDim.x + threadIdx.x) >> 5;
    int lane = threadIdx.x & 31;
    if (warp >= NN) return;
    int rs = g_rs[warp];
    int d  = g_deg[warp];
    const float4* X4 = (const float4*)X;
    float4 acc = make_float4(0.f, 0.f, 0.f, 0.f);
    for (int j0 = 0; j0 < d; j0 += 32) {
        int idx = 0;
        if (j0 + lane < d) idx = g_csr[rs + j0 + lane];
        int cnt = min(32, d - j0);
        for (int t = 0; t < cnt; t++) {
            int s = __shfl_sync(0xffffffffu, idx, t);
            float4 v = X4[(size_t)s * 32 + lane];
            acc.x += v.x; acc.y += v.y; acc.z += v.z; acc.w += v.w;
        }
    }
    float inv = 1.0f / fmaxf((float)d, 1.0f);
    float m[4] = { acc.x * inv, acc.y * inv, acc.z * inv, acc.w * inv };
    uint32_t hp[2], lp[2];
#pragma unroll
    for (int q = 0; q < 2; q++) {
        __nv_bfloat16 h0 = __float2bfloat16(m[2*q]);
        __nv_bfloat16 h1 = __float2bfloat16(m[2*q+1]);
        __nv_bfloat16 l0 = __float2bfloat16(m[2*q]   - __bfloat162float(h0));
        __nv_bfloat16 l1 = __float2bfloat16(m[2*q+1] - __bfloat162float(h1));
        hp[q] = (uint32_t)__bfloat16_as_ushort(h0) | ((uint32_t)__bfloat16_as_ushort(h1) << 16);
        lp[q] = (uint32_t)__bfloat16_as_ushort(l0) | ((uint32_t)__bfloat16_as_ushort(l1) << 16);
    }
    size_t o = (size_t)warp * 128 + lane * 4;
    *(uint2*)(g_mh + o) = make_uint2(hp[0], hp[1]);
    *(uint2*)(g_ml + o) = make_uint2(lp[0], lp[1]);
}

// ---------------- SAGE GEMM via mma.sync (bias + L2 norm + fused BN stats) ----------------
// smem layout (bytes); tiles are [128][136] bf16 (272B row stride; pad keeps ldmatrix conflict-free)
#define SG_AH   0
#define SG_AL   34816
#define SG_BH   69632
#define SG_BL   104448
#define SG_BIAS 139264
#define SG_INV  139776
#define SMEM_SAGE 140288

__global__ void __launch_bounds__(256, 1)
sage_mma_gemm(const __nv_bfloat16* __restrict__ Amh, const __nv_bfloat16* __restrict__ Aml,
              const __nv_bfloat16* __restrict__ Axh, const __nv_bfloat16* __restrict__ Axl,
              const __nv_bfloat16* __restrict__ Wlh, const __nv_bfloat16* __restrict__ Wll,
              const __nv_bfloat16* __restrict__ Wrh, const __nv_bfloat16* __restrict__ Wrl,
              const float* __restrict__ bias, float* __restrict__ Out)
{
    extern __shared__ char sm[];
    uint32_t sb = smem_u32(sm);
    const int tid = threadIdx.x;
    const int lane = tid & 31;
    const int wid = tid >> 5;
    const int warp_m = wid & 3;        // 4 row-groups of 32
    const int warp_n = wid >> 2;       // 2 col-groups of 64
    const int row0 = blockIdx.x * 128;

    if (tid < 128) ((float*)(sm + SG_BIAS))[tid] = bias[tid];

    float c[2][8][4];
#pragma unroll
    for (int mi = 0; mi < 2; mi++)
#pragma unroll
        for (int nf = 0; nf < 8; nf++)
#pragma unroll
            for (int q = 0; q < 4; q++) c[mi][nf][q] = 0.f;

    // precomputed ldmatrix lane addressing offsets (element units)
    const int a_r = lane & 15;
    const int a_c = (lane >> 4) << 3;
    const int b_r = (lane & 7) + ((lane >> 4) << 3);
    const int b_c = ((lane >> 3) & 1) << 3;

#pragma unroll 1
    for (int p = 0; p < 2; p++) {
        const __nv_bfloat16* Ah = p ? Axh : Amh;
        const __nv_bfloat16* Al = p ? Axl : Aml;
        const __nv_bfloat16* Bh = p ? Wrh : Wlh;
        const __nv_bfloat16* Bl = p ? Wrl : Wll;
        __syncthreads();
        // load tiles: 128 rows x 16 uint4 each
        const uint4 z4 = make_uint4(0u, 0u, 0u, 0u);
#pragma unroll
        for (int i = 0; i < 8; i++) {
            int idx = tid + i * 256;
            int row = idx >> 4;
            int c8 = idx & 15;
            int grow = row0 + row;
            uint4 vah = z4, val = z4;
            if (grow < NN) {
                vah = *(const uint4*)(Ah + (size_t)grow * 128 + c8 * 8);
                val = *(const uint4*)(Al + (size_t)grow * 128 + c8 * 8);
            }
            *(uint4*)(sm + SG_AH + row * 272 + c8 * 16) = vah;
            *(uint4*)(sm + SG_AL + row * 272 + c8 * 16) = val;
            uint4 vbh = *(const uint4*)(Bh + row * 128 + c8 * 8);
            uint4 vbl = *(const uint4*)(Bl + row * 128 + c8 * 8);
            *(uint4*)(sm + SG_BH + row * 272 + c8 * 16) = vbh;
            *(uint4*)(sm + SG_BL + row * 272 + c8 * 16) = vbl;
        }
        __syncthreads();

#pragma unroll
        for (int ks = 0; ks < 8; ks++) {
            const int k0 = ks * 16;
            uint32_t ah[8], al[8], bh[16], bl[16];
#pragma unroll
            for (int mi = 0; mi < 2; mi++) {
                uint32_t ad = sb + SG_AH +
                    (uint32_t)(((warp_m * 32 + mi * 16 + a_r) * 136 + k0 + a_c) * 2);
                LDSM4(ah[mi*4+0], ah[mi*4+1], ah[mi*4+2], ah[mi*4+3], ad);
                LDSM4(al[mi*4+0], al[mi*4+1], al[mi*4+2], al[mi*4+3],
                      ad + (SG_AL - SG_AH));
            }
#pragma unroll
            for (int pr = 0; pr < 4; pr++) {
                uint32_t bd = sb + SG_BH +
                    (uint32_t)(((warp_n * 64 + pr * 16 + b_r) * 136 + k0 + b_c) * 2);
                LDSM4(bh[pr*4+0], bh[pr*4+1], bh[pr*4+2], bh[pr*4+3], bd);
                LDSM4(bl[pr*4+0], bl[pr*4+1], bl[pr*4+2], bl[pr*4+3],
                      bd + (SG_BL - SG_BH));
            }
#pragma unroll
            for (int mi = 0; mi < 2; mi++)
#pragma unroll
                for (int nf = 0; nf < 8; nf++)
                    MMA16816(c[mi][nf], ah[mi*4+0], ah[mi*4+1], ah[mi*4+2], ah[mi*4+3],
                             bh[nf*2+0], bh[nf*2+1]);
#pragma unroll
            for (int mi = 0; mi < 2; mi++)
#pragma unroll
                for (int nf = 0; nf < 8; nf++)
                    MMA16816(c[mi][nf], al[mi*4+0], al[mi*4+1], al[mi*4+2], al[mi*4+3],
                             bh[nf*2+0], bh[nf*2+1]);
#pragma unroll
            for (int mi = 0; mi < 2; mi++)
#pragma unroll
                for (int nf = 0; nf < 8; nf++)
                    MMA16816(c[mi][nf], ah[mi*4+0], ah[mi*4+1], ah[mi*4+2], ah[mi*4+3],
                             bl[nf*2+0], bl[nf*2+1]);
        }
    }

    // ---- epilogue: bias -> smem, L2 norm, BN partial stats ----
    __syncthreads();
    float* yp = (float*)sm;               // [128][132] overlay on tiles
    const float* sbias = (const float*)(sm + SG_BIAS);
    const int g = lane >> 2, t2 = (lane & 3) * 2;
#pragma unroll
    for (int mi = 0; mi < 2; mi++)
#pragma unroll
        for (int nf = 0; nf < 8; nf++) {
            int ra = warp_m * 32 + mi * 16 + g;
            int col = warp_n * 64 + nf * 8 + t2;
            float b0 = sbias[col], b1 = sbias[col + 1];
            *(float2*)(yp + ra * 132 + col) =
                make_float2(c[mi][nf][0] + b0, c[mi][nf][1] + b1);
            *(float2*)(yp + (ra + 8) * 132 + col) =
                make_float2(c[mi][nf][2] + b0, c[mi][nf][3] + b1);
        }
    __syncthreads();
    float* sinv = (float*)(sm + SG_INV);
    if (tid < 128) {
        float s = 0.f;
#pragma unroll
        for (int j = 0; j < 32; j++) {
            float4 v = *(float4*)(yp + tid * 132 + j * 4);
            s = fmaf(v.x, v.x, s); s = fmaf(v.y, v.y, s);
            s = fmaf(v.z, v.z, s); s = fmaf(v.w, v.w, s);
        }
        sinv[tid] = 1.0f / fmaxf(sqrtf(s), 1e-12f);
    }
    __syncthreads();

    float cs[4] = {0.f, 0.f, 0.f, 0.f};
    float cq[4] = {0.f, 0.f, 0.f, 0.f};
#pragma unroll
    for (int rr = 0; rr < 16; rr++) {
        int row = wid * 16 + rr;
        int grow = row0 + row;
        if (grow < NN) {
            float inv = sinv[row];
            float4 y4 = *(float4*)(yp + row * 132 + lane * 4);
            y4.x *= inv; y4.y *= inv; y4.z *= inv; y4.w *= inv;
            *(float4*)(Out + (size_t)grow * 128 + lane * 4) = y4;
            cs[0] += y4.x; cs[1] += y4.y; cs[2] += y4.z; cs[3] += y4.w;
            cq[0] = fmaf(y4.x, y4.x, cq[0]); cq[1] = fmaf(y4.y, y4.y, cq[1]);
            cq[2] = fmaf(y4.z, y4.z, cq[2]); cq[3] = fmaf(y4.w, y4.w, cq[3]);
        }
    }
#pragma unroll
    for (int j = 0; j < 4; j++) {
        atomicAdd(&g_colsum[lane * 4 + j], cs[j]);
        atomicAdd(&g_colsq[lane * 4 + j], cq[j]);
    }
}

// ---------------- output GEMM via mma.sync + fused log_softmax ----------------
#define OG_AH   0
#define OG_AL   34816
#define OG_BH   69632
#define OG_BL   87040
#define OG_BIAS 104448
#define SMEM_OUT 104704

__global__ void __launch_bounds__(256, 1)
out_mma_gemm(const __nv_bfloat16* __restrict__ Ah_g, const __nv_bfloat16* __restrict__ Al_g,
             const __nv_bfloat16* __restrict__ Bh_g, const __nv_bfloat16* __restrict__ Bl_g,
             const float* __restrict__ bias, float* __restrict__ Out)
{
    extern __shared__ char sm[];
    uint32_t sb = smem_u32(sm);
    const int tid = threadIdx.x;
    const int lane = tid & 31;
    const int wid = tid >> 5;          // 8 warps, each owns 16 rows
    const int row0 = blockIdx.x * 128;

    if (tid < 64) ((float*)(sm + OG_BIAS))[tid] = bias[tid];

    // load tiles
    const uint4 z4 = make_uint4(0u, 0u, 0u, 0u);
#pragma unroll
    for (int i = 0; i < 8; i++) {
        int idx = tid + i * 256;
        int row = idx >> 4;
        int c8 = idx & 15;
        int grow = row0 + row;
        uint4 vah = z4, val = z4;
        if (grow < NN) {
            vah = *(const uint4*)(Ah_g + (size_t)grow * 128 + c8 * 8);
            val = *(const uint4*)(Al_g + (size_t)grow * 128 + c8 * 8);
        }
        *(uint4*)(sm + OG_AH + row * 272 + c8 * 16) = vah;
        *(uint4*)(sm + OG_AL + row * 272 + c8 * 16) = val;
    }
#pragma unroll
    for (int i = 0; i < 4; i++) {
        int idx = tid + i * 256;
        int row = idx >> 4;             // 0..63
        int c8 = idx & 15;
        uint4 vbh = *(const uint4*)(Bh_g + row * 128 + c8 * 8);
        uint4 vbl = *(const uint4*)(Bl_g + row * 128 + c8 * 8);
        *(uint4*)(sm + OG_BH + row * 272 + c8 * 16) = vbh;
        *(uint4*)(sm + OG_BL + row * 272 + c8 * 16) = vbl;
    }
    __syncthreads();

    float c[8][4];
#pragma unroll
    for (int nf = 0; nf < 8; nf++)
#pragma unroll
        for (int q = 0; q < 4; q++) c[nf][q] = 0.f;

    const int a_r = lane & 15;
    const int a_c = (lane >> 4) << 3;
    const int b_r = (lane & 7) + ((lane >> 4) << 3);
    const int b_c = ((lane >> 3) & 1) << 3;

#pragma unroll
    for (int ks = 0; ks < 8; ks++) {
        const int k0 = ks * 16;
        uint32_t ah[4], al[4], bh[16], bl[16];
        uint32_t ad = sb + OG_AH + (uint32_t)(((wid * 16 + a_r) * 136 + k0 + a_c) * 2);
        LDSM4(ah[0], ah[1], ah[2], ah[3], ad);
        LDSM4(al[0], al[1], al[2], al[3], ad + (OG_AL - OG_AH));
#pragma unroll
        for (int pr = 0; pr < 4; pr++) {
            uint32_t bd = sb + OG_BH + (uint32_t)(((pr * 16 + b_r) * 136 + k0 + b_c) * 2);
            LDSM4(bh[pr*4+0], bh[pr*4+1], bh[pr*4+2], bh[pr*4+3], bd);
            LDSM4(bl[pr*4+0], bl[pr*4+1], bl[pr*4+2], bl[pr*4+3], bd + (OG_BL - OG_BH));
        }
#pragma unroll
        for (int nf = 0; nf < 8; nf++)
            MMA16816(c[nf], ah[0], ah[1], ah[2], ah[3], bh[nf*2+0], bh[nf*2+1]);
#pragma unroll
        for (int nf = 0; nf < 8; nf++)
            MMA16816(c[nf], al[0], al[1], al[2], al[3], bh[nf*2+0], bh[nf*2+1]);
#pragma unroll
        for (int nf = 0; nf < 8; nf++)
            MMA16816(c[nf], ah[0], ah[1], ah[2], ah[3], bl[nf*2+0], bl[nf*2+1]);
    }

    // epilogue: bias + log_softmax per row
    __syncthreads();
    float* yp = (float*)sm;   // [128][68] overlay
    const float* sbias = (const float*)(sm + OG_BIAS);
    const int g = lane >> 2, t2 = (lane & 3) * 2;
#pragma unroll
    for (int nf = 0; nf < 8; nf++) {
        int ra = wid * 16 + g;
        int col = nf * 8 + t2;
        float b0 = sbias[col], b1 = sbias[col + 1];
        *(float2*)(yp + ra * 68 + col) = make_float2(c[nf][0] + b0, c[nf][1] + b1);
        *(float2*)(yp + (ra + 8) * 68 + col) = make_float2(c[nf][2] + b0, c[nf][3] + b1);
    }
    __syncthreads();
    if (tid < 128) {
        float y[64];
#pragma unroll
        for (int j = 0; j < 16; j++)
            *(float4*)&y[j * 4] = *(float4*)(yp + tid * 68 + j * 4);
        float m = -1e30f;
#pragma unroll
        for (int j = 0; j < 64; j++) m = fmaxf(m, y[j]);
        float s = 0.f;
#pragma unroll
        for (int j = 0; j < 64; j++) s += expf(y[j] - m);
        float lse = m + logf(s);
#pragma unroll
        for (int j = 0; j < 16; j++) {
            float4 v = *(float4*)&y[j * 4];
            v.x -= lse; v.y -= lse; v.z -= lse; v.w -= lse;
            *(float4*)(yp + tid * 68 + j * 4) = v;
        }
    }
    __syncthreads();
#pragma unroll
    for (int rr = 0; rr < 16; rr++) {
        int row = wid * 16 + rr;
        int grow = row0 + row;
        if (grow < NN) {
            float2 v = *(float2*)(yp + row * 68 + lane * 2);
            *(float2*)(Out + (size_t)grow * 64 + lane * 2) = v;
        }
    }
}

// ---------------- batch norm ----------------
__global__ void zero_bn_k() {
    int t = threadIdx.x;
    if (t < HH) { g_colsum[t] = 0.f; g_colsq[t] = 0.f; }
}

__global__ void bn_finalize_k(const float* __restrict__ gamma, const float* __restrict__ beta) {
    int c = threadIdx.x;
    if (c >= HH) return;
    float mu  = g_colsum[c] * (1.0f / NN);
    float var = g_colsq[c] * (1.0f / NN) - mu * mu;
    float sc  = gamma[c] * rsqrtf(var + 1e-5f);
    g_scale[c] = sc;
    g_shift[c] = beta[c] - mu * sc;
}

// bn+relu -> h1 fp32 (residual) and hi/lo bf16 (conv2 Xr operand)
__global__ void bn_apply1_k(const float* __restrict__ pre) {
    int idx = blockIdx.x * blockDim.x + threadIdx.x;
    if (idx >= NN * HH) return;
    int col = idx & 127;
    float v = fmaf(pre[idx], g_scale[col], g_shift[col]);
    v = fmaxf(v, 0.f);
    g_h1[idx] = v;
    __nv_bfloat16 h = __float2bfloat16(v);
    g_xh[idx] = h;
    g_xl[idx] = __float2bfloat16(v - __bfloat162float(h));
}

// bn+relu+residual -> hfinal hi/lo (out GEMM A operand; reuses g_mh/g_ml)
__global__ void bn_apply2_k(const float* __restrict__ pre) {
    int idx = blockIdx.x * blockDim.x + threadIdx.x;
    if (idx >= NN * HH) return;
    int col = idx & 127;
    float v = fmaf(pre[idx], g_scale[col], g_shift[col]);
    v = fmaxf(v, 0.f) + g_h1[idx];
    __nv_bfloat16 h = __float2bfloat16(v);
    g_mh[idx] = h;
    g_ml[idx] = __float2bfloat16(v - __bfloat162float(h));
}

// ---------------- launch ----------------
extern "C" void kernel_launch(void* const* d_in, const int* in_sizes, int n_in,
                              void* d_out, int out_size) {
    const float* x    = (const float*)d_in[0];
    const int*   ei   = (const int*)  d_in[1];
    const float* W1l  = (const float*)d_in[2];
    const float* b1l  = (const float*)d_in[3];
    const float* W1r  = (const float*)d_in[4];
    const float* g1   = (const float*)d_in[5];
    const float* be1  = (const float*)d_in[6];
    const float* W2l  = (const float*)d_in[7];
    const float* b2l  = (const float*)d_in[8];
    const float* W2r  = (const float*)d_in[9];
    const float* g2   = (const float*)d_in[10];
    const float* be2  = (const float*)d_in[11];
    const float* Wout = (const float*)d_in[12];
    const float* bout = (const float*)d_in[13];
    float* out = (float*)d_out;

    float *p_pre, *p_h1;
    __nv_bfloat16 *p_mh, *p_ml, *p_xh, *p_xl, *p_wh, *p_wl;
    cudaGetSymbolAddress((void**)&p_pre, g_pre);
    cudaGetSymbolAddress((void**)&p_h1,  g_h1);
    cudaGetSymbolAddress((void**)&p_mh,  g_mh);
    cudaGetSymbolAddress((void**)&p_ml,  g_ml);
    cudaGetSymbolAddress((void**)&p_xh,  g_xh);
    cudaGetSymbolAddress((void**)&p_xl,  g_xl);
    cudaGetSymbolAddress((void**)&p_wh,  g_wh);
    cudaGetSymbolAddress((void**)&p_wl,  g_wl);

    cudaFuncSetAttribute(sage_mma_gemm, cudaFuncAttributeMaxDynamicSharedMemorySize, SMEM_SAGE);
    cudaFuncSetAttribute(out_mma_gemm,  cudaFuncAttributeMaxDynamicSharedMemorySize, SMEM_OUT);

    const int ETHREADS = 256;
    const int EGRID = (EE + ETHREADS - 1) / ETHREADS;
    const int GEMM_GRID = (NN + 127) / 128;        // 782
    const int AGG_GRID = (NN * 32 + 255) / 256;    // 12500
    const int EW_GRID = (NN * HH) / 256;           // 50000

    // edge preprocessing (shared by both convs)
    detect_k<<<1, 1>>>(ei);
    zero_deg_k<<<(NN + 255) / 256, 256>>>();
    edge_conv_k<<<EGRID, ETHREADS>>>(ei);
    scan1_k<<<SCAN_BLOCKS, 1024>>>();
    scan2_k<<<1, 1>>>();
    scan3_k<<<SCAN_BLOCKS, 1024>>>();
    csr_fill_k<<<EGRID, ETHREADS>>>();

    // conversions
    wprep_k<<<(4 * 16384 + 8192 + 255) / 256, 256>>>(W1l, W1r, W2l, W2r, Wout);
    xconv_k<<<EW_GRID, 256>>>(x);

    // ---- conv1 ----
    aggregate_k<<<AGG_GRID, 256>>>(x);
    zero_bn_k<<<1, 128>>>();
    sage_mma_gemm<<<GEMM_GRID, 256, SMEM_SAGE>>>(p_mh, p_ml, p_xh, p_xl,
                                                 p_wh, p_wl, p_wh + 16384, p_wl + 16384,
                                                 b1l, p_pre);
    bn_finalize_k<<<1, 128>>>(g1, be1);
    bn_apply1_k<<<EW_GRID, 256>>>(p_pre);

    // ---- conv2 (+ residual) ----
    aggregate_k<<<AGG_GRID, 256>>>(p_h1);
    zero_bn_k<<<1, 128>>>();
    sage_mma_gemm<<<GEMM_GRID, 256, SMEM_SAGE>>>(p_mh, p_ml, p_xh, p_xl,
                                                 p_wh + 32768, p_wl + 32768,
                                                 p_wh + 49152, p_wl + 49152,
                                                 b2l, p_pre);
    bn_finalize_k<<<1, 128>>>(g2, be2);
    bn_apply2_k<<<EW_GRID, 256>>>(p_pre);

    // ---- output head (fused log_softmax) ----
    out_mma_gemm<<<GEMM_GRID, 256, SMEM_OUT>>>(p_mh, p_ml,
                                               p_wh + 65536, p_wl + 65536,
                                               bout, out);
}